// round 1
// baseline (speedup 1.0000x reference)
#include <cuda_runtime.h>
#include <math.h>

#define B_    4
#define C_    128
#define T_    2000
#define K_    31
#define H_    512
#define MAXO_ 204
#define BT_   (B_ * T_)     // 8000
#define CT_   (C_ * T_)     // 256000
#define NOUT_ 257

__constant__ int c_bw[K_]   = {2,3,3,3,3,3,3,3,3,3,3,8,8,8,8,8,8,8,8,8,8,8,8,16,16,16,16,16,16,16,17};
__constant__ int c_base[K_] = {0,2,5,8,11,14,17,20,23,26,29,32,40,48,56,64,72,80,88,96,104,112,120,128,144,160,176,192,208,224,240};

// ---- scratch (device globals; no allocation allowed) ----
__device__ float g_sum [B_ * K_];
__device__ float g_sq  [B_ * K_];
__device__ float g_mean[B_ * K_];
__device__ float g_istd[B_ * K_];
__device__ float g_xn[(size_t)K_ * BT_ * C_];   // [K][B*T][C]  ~127 MB
__device__ float g_h [(size_t)K_ * BT_ * H_];   // [K][B*T][H]  ~508 MB

// ============================================================
// 0) zero the stat accumulators (graph replays re-run this)
// ============================================================
__global__ void zero_stats_kernel() {
    int i = threadIdx.x;
    if (i < B_ * K_) { g_sum[i] = 0.f; g_sq[i] = 0.f; }
}

// ============================================================
// 1) partial sums for mean/var per (b,k).
//    lane = k -> warp reads 31 consecutive floats per (c,t) row.
//    grid: (64, B_), block: 256 (8 warps)
// ============================================================
__global__ __launch_bounds__(256) void stats_kernel(const float* __restrict__ x) {
    const int b    = blockIdx.y;
    const int lane = threadIdx.x & 31;
    const int warp = threadIdx.x >> 5;
    const int ROWS_PER_BLOCK = CT_ / 64;           // 4000
    const int ROWS_PER_WARP  = ROWS_PER_BLOCK / 8; // 500
    const int r0 = blockIdx.x * ROWS_PER_BLOCK + warp * ROWS_PER_WARP;

    float s = 0.f, q = 0.f;
    if (lane < K_) {
        const float* p = x + (size_t)b * CT_ * K_ + (size_t)r0 * K_ + lane;
        #pragma unroll 4
        for (int r = 0; r < ROWS_PER_WARP; ++r) {
            float v = p[(size_t)r * K_];
            s += v; q += v * v;
        }
    }
    __shared__ float ss[8][32], sq[8][32];
    ss[warp][lane] = s; sq[warp][lane] = q;
    __syncthreads();
    if (warp == 0 && lane < K_) {
        float S = 0.f, Q = 0.f;
        #pragma unroll
        for (int w = 0; w < 8; ++w) { S += ss[w][lane]; Q += sq[w][lane]; }
        atomicAdd(&g_sum[b * K_ + lane], S);
        atomicAdd(&g_sq [b * K_ + lane], Q);
    }
}

// ============================================================
// 2) finalize mean / inv_std
// ============================================================
__global__ void finalize_stats_kernel() {
    int i = threadIdx.x;
    if (i < B_ * K_) {
        const float n = (float)CT_;
        float m = g_sum[i] / n;
        float v = g_sq[i] / n - m * m;
        g_mean[i] = m;
        g_istd[i] = rsqrtf(v + 1e-5f);
    }
}

// ============================================================
// 3) normalize + affine + transpose: x[B,C,T,K] -> xn[K][B*T][C]
//    Tile: fixed b, TT time steps, all k, all c. Both global
//    read and write phases are coalesced via an smem tile.
//    grid: (T_/TT, B_), block: 256
// ============================================================
#define TT 2
__global__ __launch_bounds__(256) void norm_transpose_kernel(
        const float* __restrict__ x,
        const float* __restrict__ nw,
        const float* __restrict__ nb) {
    __shared__ float tile[TT][K_][C_ + 1];   // ~32 KB, conflict-free both phases
    const int b  = blockIdx.y;
    const int t0 = blockIdx.x * TT;
    const int NEL = C_ * TT * K_;            // 7936

    // read phase: consecutive idx -> contiguous (t,k) span per c
    for (int idx = threadIdx.x; idx < NEL; idx += blockDim.x) {
        int c = idx / (TT * K_);
        int r = idx % (TT * K_);
        int t = r / K_;
        int k = r % K_;
        float v = x[(((size_t)b * C_ + c) * T_ + (t0 + t)) * K_ + k];
        int bk = b * K_ + k;
        v = (v - g_mean[bk]) * g_istd[bk] * nw[k * C_ + c] + nb[k * C_ + c];
        tile[t][k][c] = v;
    }
    __syncthreads();
    // write phase: c contiguous
    for (int idx = threadIdx.x; idx < NEL; idx += blockDim.x) {
        int row = idx / C_;       // 0..61
        int c   = idx % C_;
        int k   = row >> 1;
        int t   = row & 1;
        g_xn[((size_t)k * BT_ + (size_t)b * T_ + t0 + t) * C_ + c] = tile[t][k][c];
    }
}

// ============================================================
// 4) fc1: per band h = tanh(xn @ W1^T + b1)
//    NT GEMM, 64x64 tile, TK=16, 4x4 per thread.
//    grid: (BT_/64=125, H_/64=8, K_), block 256
// ============================================================
__global__ __launch_bounds__(256) void fc1_kernel(
        const float* __restrict__ w1, const float* __restrict__ b1) {
    const int band = blockIdx.z;
    const int m0 = blockIdx.x * 64;
    const int n0 = blockIdx.y * 64;
    const float* A = g_xn + (size_t)band * BT_ * C_;   // [8000][128]
    const float* W = w1   + (size_t)band * H_  * C_;   // [512][128]

    __shared__ float As[16][68];   // [kk][m], rows 16B aligned
    __shared__ float Bs[16][68];   // [kk][n]

    const int tid = threadIdx.x;
    const int tx = tid & 15, ty = tid >> 4;
    const int lr = tid >> 2;            // 0..63
    const int lc = (tid & 3) * 4;       // float4 col in k-chunk

    float acc[4][4] = {};
    for (int kc = 0; kc < C_; kc += 16) {
        float4 a = *(const float4*)&A[(size_t)(m0 + lr) * C_ + kc + lc];
        float4 w = *(const float4*)&W[(size_t)(n0 + lr) * C_ + kc + lc];
        As[lc+0][lr] = a.x; As[lc+1][lr] = a.y; As[lc+2][lr] = a.z; As[lc+3][lr] = a.w;
        Bs[lc+0][lr] = w.x; Bs[lc+1][lr] = w.y; Bs[lc+2][lr] = w.z; Bs[lc+3][lr] = w.w;
        __syncthreads();
        #pragma unroll
        for (int kk = 0; kk < 16; ++kk) {
            float4 ar = *(const float4*)&As[kk][ty * 4];
            float4 br = *(const float4*)&Bs[kk][tx * 4];
            float av[4] = {ar.x, ar.y, ar.z, ar.w};
            float bv[4] = {br.x, br.y, br.z, br.w};
            #pragma unroll
            for (int i = 0; i < 4; ++i)
                #pragma unroll
                for (int j = 0; j < 4; ++j)
                    acc[i][j] += av[i] * bv[j];
        }
        __syncthreads();
    }
    float* Hout = g_h + (size_t)band * BT_ * H_;
    #pragma unroll
    for (int i = 0; i < 4; ++i) {
        const int m = m0 + ty * 4 + i;
        #pragma unroll
        for (int j = 0; j < 4; ++j) {
            const int n = n0 + tx * 4 + j;
            Hout[(size_t)m * H_ + n] = tanhf(acc[i][j] + b1[band * H_ + n]);
        }
    }
}

// ============================================================
// 5) fc2 + GLU + scatter to output layout [B,257,T,3,2].
//    Each output column j in [0, 6*bw) needs two dot products:
//    row j (a) and row j+6bw (g) of fc2_w. GLU in-thread.
//    64 rows x 32 cols per block, 4x2 (x2 for a/g) per thread.
//    grid: (125, 4, K_), block 256
// ============================================================
__global__ __launch_bounds__(256) void fc2_kernel(
        const float* __restrict__ w2, const float* __restrict__ b2,
        float* __restrict__ out) {
    const int band = blockIdx.z;
    const int bw   = c_bw[band];
    const int neff = 6 * bw;
    const int j0   = blockIdx.y * 32;
    if (j0 >= neff) return;
    const int m0 = blockIdx.x * 64;

    const float* A = g_h + (size_t)band * BT_ * H_;     // [8000][512]
    const float* W = w2  + (size_t)band * MAXO_ * H_;   // [204][512]

    __shared__ float As[16][68];
    __shared__ float Wa[16][36];
    __shared__ float Wg[16][36];

    const int tid = threadIdx.x;
    const int tx = tid & 15, ty = tid >> 4;

    float ca[4][2] = {}, cg[4][2] = {};
    for (int kc = 0; kc < H_; kc += 16) {
        {   // A: 64 rows x 16
            int lr = tid >> 2, lc = (tid & 3) * 4;
            float4 a = *(const float4*)&A[(size_t)(m0 + lr) * H_ + kc + lc];
            As[lc+0][lr] = a.x; As[lc+1][lr] = a.y; As[lc+2][lr] = a.z; As[lc+3][lr] = a.w;
        }
        {   // Wa / Wg: 32 rows x 16 each, split across thread halves
            int half = tid >> 7;          // 0 -> Wa, 1 -> Wg
            int t2 = tid & 127;
            int lr = t2 >> 2;             // 0..31
            int lc = (t2 & 3) * 4;
            int j  = j0 + lr;
            float4 v = make_float4(0.f, 0.f, 0.f, 0.f);
            if (j < neff) {
                int row = j + half * neff;
                v = *(const float4*)&W[(size_t)row * H_ + kc + lc];
            }
            float (*S)[36] = half ? Wg : Wa;
            S[lc+0][lr] = v.x; S[lc+1][lr] = v.y; S[lc+2][lr] = v.z; S[lc+3][lr] = v.w;
        }
        __syncthreads();
        #pragma unroll
        for (int kk = 0; kk < 16; ++kk) {
            float4 ar = *(const float4*)&As[kk][ty * 4];
            float2 wa = *(const float2*)&Wa[kk][tx * 2];
            float2 wg = *(const float2*)&Wg[kk][tx * 2];
            float av[4] = {ar.x, ar.y, ar.z, ar.w};
            float wav[2] = {wa.x, wa.y};
            float wgv[2] = {wg.x, wg.y};
            #pragma unroll
            for (int i = 0; i < 4; ++i)
                #pragma unroll
                for (int j = 0; j < 2; ++j) {
                    ca[i][j] += av[i] * wav[j];
                    cg[i][j] += av[i] * wgv[j];
                }
        }
        __syncthreads();
    }
    const int base = c_base[band];
    #pragma unroll
    for (int i = 0; i < 4; ++i) {
        const int m = m0 + ty * 4 + i;
        const int b = m / T_;
        const int t = m % T_;
        #pragma unroll
        for (int j = 0; j < 2; ++j) {
            const int jj = j0 + tx * 2 + j;
            if (jj < neff) {
                float a = ca[i][j] + b2[band * MAXO_ + jj];
                float g = cg[i][j] + b2[band * MAXO_ + neff + jj];
                float r = a / (1.f + expf(-g));          // a * sigmoid(g)
                int wv  = jj / 6;
                int rem = jj - wv * 6;
                out[(((size_t)b * NOUT_ + base + wv) * T_ + t) * 6 + rem] = r;
            }
        }
    }
}

// ============================================================
extern "C" void kernel_launch(void* const* d_in, const int* in_sizes, int n_in,
                              void* d_out, int out_size) {
    const float* x  = (const float*)d_in[0];
    const float* nw = (const float*)d_in[1];
    const float* nb = (const float*)d_in[2];
    const float* w1 = (const float*)d_in[3];
    const float* b1 = (const float*)d_in[4];
    const float* w2 = (const float*)d_in[5];
    const float* b2 = (const float*)d_in[6];
    float* out = (float*)d_out;

    zero_stats_kernel<<<1, 128>>>();
    stats_kernel<<<dim3(64, B_), 256>>>(x);
    finalize_stats_kernel<<<1, 128>>>();
    norm_transpose_kernel<<<dim3(T_ / TT, B_), 256>>>(x, nw, nb);
    fc1_kernel<<<dim3(BT_ / 64, H_ / 64, K_), 256>>>(w1, b1);
    fc2_kernel<<<dim3(BT_ / 64, 4, K_), 256>>>(w2, b2, out);
}

// round 5
// speedup vs baseline: 1.0602x; 1.0602x over previous
#include <cuda_runtime.h>
#include <cuda_bf16.h>
#include <math.h>
#include <stdint.h>

#define B_    4
#define C_    128
#define T_    2000
#define K_    31
#define H_    512
#define MAXO_ 204
#define BT_   (B_ * T_)       // 8000
#define BTP_  8064            // padded to 63*128
#define CT_   (C_ * T_)       // 256000
#define NOUT_ 257
#define W2R_  208             // max padded fc2 rows

__constant__ int c_bw[K_]   = {2,3,3,3,3,3,3,3,3,3,3,8,8,8,8,8,8,8,8,8,8,8,8,16,16,16,16,16,16,16,17};
__constant__ int c_base[K_] = {0,2,5,8,11,14,17,20,23,26,29,32,40,48,56,64,72,80,88,96,104,112,120,128,144,160,176,192,208,224,240};

// ---- scratch (device globals; zero-initialized at module load) ----
__device__ float g_sum [B_ * K_];
__device__ float g_sq  [B_ * K_];
__device__ float g_mean[B_ * K_];
__device__ float g_istd[B_ * K_];
__device__ __nv_bfloat16 g_xnh[(size_t)K_ * BTP_ * C_];   // xn hi  [K][BTP][C]
__device__ __nv_bfloat16 g_xnl[(size_t)K_ * BTP_ * C_];   // xn lo
__device__ __nv_bfloat16 g_hh [(size_t)K_ * BTP_ * H_];   // h hi   [K][BTP][H]
__device__ __nv_bfloat16 g_hl [(size_t)K_ * BTP_ * H_];   // h lo
__device__ __nv_bfloat16 g_w1h[(size_t)K_ * H_ * C_];     // fc1 w hi [K][H][C]
__device__ __nv_bfloat16 g_w1l[(size_t)K_ * H_ * C_];
__device__ __nv_bfloat16 g_w2h[(size_t)K_ * W2R_ * H_];   // fc2 w hi, a|pad|g|pad rows
__device__ __nv_bfloat16 g_w2l[(size_t)K_ * W2R_ * H_];

// ============================================================
// helpers (plain sm_103-safe: ldmatrix + mma.sync only)
// ============================================================
static __device__ __forceinline__ uint32_t smem_u32(const void* p) {
    return (uint32_t)__cvta_generic_to_shared(p);
}

#define LDSM4(r, addr)                                                           \
    asm volatile("ldmatrix.sync.aligned.m8n8.x4.shared.b16 {%0,%1,%2,%3}, [%4];" \
        : "=r"((r)[0]), "=r"((r)[1]), "=r"((r)[2]), "=r"((r)[3]) : "r"(addr))

#define LDSM2(r, addr)                                                           \
    asm volatile("ldmatrix.sync.aligned.m8n8.x2.shared.b16 {%0,%1}, [%2];"       \
        : "=r"((r)[0]), "=r"((r)[1]) : "r"(addr))

#define MMA16816(d, a, b0v, b1v)                                                 \
    asm volatile("mma.sync.aligned.m16n8k16.row.col.f32.bf16.bf16.f32 "          \
        "{%0,%1,%2,%3}, {%4,%5,%6,%7}, {%8,%9}, {%0,%1,%2,%3};"                  \
        : "+f"((d)[0]), "+f"((d)[1]), "+f"((d)[2]), "+f"((d)[3])                 \
        : "r"((a)[0]), "r"((a)[1]), "r"((a)[2]), "r"((a)[3]), "r"(b0v), "r"(b1v))

// copy [rows x 128] bf16 from global (row stride gstride) into smem rows of
// 272 bytes (128 cols + 8-col pad -> conflict-free ldmatrix)
static __device__ __forceinline__ void fill_pad(char* dst, const __nv_bfloat16* src,
                                                int gstride, int rows, int tid) {
    const int total = rows * 16;                 // 16B chunks
    for (int i = tid; i < total; i += 256) {
        int r = i >> 4, cb = i & 15;
        *(uint4*)(dst + r * 272 + cb * 16) =
            *(const uint4*)(src + (size_t)r * gstride + cb * 8);
    }
}

static __device__ __forceinline__ float tanh_fast(float x) {
    float e = __expf(2.0f * x);
    return 1.0f - __fdividef(2.0f, e + 1.0f);
}

static __device__ __forceinline__ void store_split(__nv_bfloat16* Hh, __nv_bfloat16* Hl,
                                                   size_t off, float v0, float v1) {
    __nv_bfloat16 h0 = __float2bfloat16(v0), h1 = __float2bfloat16(v1);
    __nv_bfloat16 l0 = __float2bfloat16(v0 - __bfloat162float(h0));
    __nv_bfloat16 l1 = __float2bfloat16(v1 - __bfloat162float(h1));
    uint32_t hp = (uint32_t)__bfloat16_as_ushort(h0) | ((uint32_t)__bfloat16_as_ushort(h1) << 16);
    uint32_t lp = (uint32_t)__bfloat16_as_ushort(l0) | ((uint32_t)__bfloat16_as_ushort(l1) << 16);
    *(uint32_t*)(Hh + off) = hp;
    *(uint32_t*)(Hl + off) = lp;
}

// ============================================================
// stats
// ============================================================
__global__ void zero_stats_kernel() {
    int i = threadIdx.x;
    if (i < B_ * K_) { g_sum[i] = 0.f; g_sq[i] = 0.f; }
}

__global__ __launch_bounds__(256) void stats_kernel(const float* __restrict__ x) {
    const int b    = blockIdx.y;
    const int lane = threadIdx.x & 31;
    const int warp = threadIdx.x >> 5;
    const int ROWS_PER_BLOCK = CT_ / 64;           // 4000
    const int ROWS_PER_WARP  = ROWS_PER_BLOCK / 8; // 500
    const int r0 = blockIdx.x * ROWS_PER_BLOCK + warp * ROWS_PER_WARP;

    float s = 0.f, q = 0.f;
    if (lane < K_) {
        const float* p = x + (size_t)b * CT_ * K_ + (size_t)r0 * K_ + lane;
        #pragma unroll 8
        for (int r = 0; r < ROWS_PER_WARP; ++r) {
            float v = p[(size_t)r * K_];
            s += v; q += v * v;
        }
    }
    __shared__ float ss[8][32], sq[8][32];
    ss[warp][lane] = s; sq[warp][lane] = q;
    __syncthreads();
    if (warp == 0 && lane < K_) {
        float S = 0.f, Q = 0.f;
        #pragma unroll
        for (int w = 0; w < 8; ++w) { S += ss[w][lane]; Q += sq[w][lane]; }
        atomicAdd(&g_sum[b * K_ + lane], S);
        atomicAdd(&g_sq [b * K_ + lane], Q);
    }
}

__global__ void finalize_stats_kernel() {
    int i = threadIdx.x;
    if (i < B_ * K_) {
        const float n = (float)CT_;
        float m = g_sum[i] / n;
        float v = g_sq[i] / n - m * m;
        g_mean[i] = m;
        g_istd[i] = rsqrtf(v + 1e-5f);
    }
}

// ============================================================
// normalize + affine + transpose + bf16 hi/lo split
// ============================================================
#define TT 2
__global__ __launch_bounds__(256) void norm_transpose_kernel(
        const float* __restrict__ x,
        const float* __restrict__ nw,
        const float* __restrict__ nb) {
    __shared__ float tile[TT][K_][C_ + 1];
    const int b  = blockIdx.y;
    const int t0 = blockIdx.x * TT;
    const int NEL = C_ * TT * K_;

    for (int idx = threadIdx.x; idx < NEL; idx += blockDim.x) {
        int c = idx / (TT * K_);
        int r = idx % (TT * K_);
        int t = r / K_;
        int k = r % K_;
        float v = x[(((size_t)b * C_ + c) * T_ + (t0 + t)) * K_ + k];
        int bk = b * K_ + k;
        v = (v - g_mean[bk]) * g_istd[bk] * nw[k * C_ + c] + nb[k * C_ + c];
        tile[t][k][c] = v;
    }
    __syncthreads();
    for (int idx = threadIdx.x; idx < NEL; idx += blockDim.x) {
        int row = idx / C_;
        int c   = idx % C_;
        int k   = row >> 1;
        int t   = row & 1;
        float v = tile[t][k][c];
        __nv_bfloat16 hi = __float2bfloat16(v);
        __nv_bfloat16 lo = __float2bfloat16(v - __bfloat162float(hi));
        size_t o = ((size_t)k * BTP_ + (size_t)b * T_ + t0 + t) * C_ + c;
        g_xnh[o] = hi;
        g_xnl[o] = lo;
    }
}

// ============================================================
// weight splits
// ============================================================
__global__ void split_w1_kernel(const float* __restrict__ w1) {
    size_t n = (size_t)K_ * H_ * C_;
    for (size_t i = blockIdx.x * blockDim.x + threadIdx.x; i < n;
         i += (size_t)gridDim.x * blockDim.x) {
        float v = w1[i];
        __nv_bfloat16 hi = __float2bfloat16(v);
        g_w1h[i] = hi;
        g_w1l[i] = __float2bfloat16(v - __bfloat162float(hi));
    }
}

__global__ void split_w2_kernel(const float* __restrict__ w2) {
    size_t n = (size_t)K_ * W2R_ * H_;
    for (size_t i = blockIdx.x * blockDim.x + threadIdx.x; i < n;
         i += (size_t)gridDim.x * blockDim.x) {
        int c = (int)(i % H_);
        int r = (int)((i / H_) % W2R_);
        int k = (int)(i / ((size_t)W2R_ * H_));
        int neff6 = 6 * c_bw[k];
        int half  = ((neff6 + 7) >> 3) << 3;
        float v = 0.f;
        if (r < half) {
            if (r < neff6) v = w2[((size_t)k * MAXO_ + r) * H_ + c];
        } else {
            int gidx = r - half;
            if (gidx < neff6) v = w2[((size_t)k * MAXO_ + neff6 + gidx) * H_ + c];
        }
        __nv_bfloat16 hi = __float2bfloat16(v);
        g_w2h[i] = hi;
        g_w2l[i] = __float2bfloat16(v - __bfloat162float(hi));
    }
}

// ============================================================
// fc1: HMMA bf16-split GEMM, h = tanh(xn @ W1^T + b1)
// block 128x64, K=128 resident. 8 warps = 4m x 2n, warp 32x32.
// smem: A_hi[128][136] A_lo W_hi[64][136] W_lo (272B rows)
// ============================================================
#define FC1_SMEM (2 * 34816 + 2 * 17408)   // 104448

__global__ __launch_bounds__(256) void fc1_kernel(const float* __restrict__ b1) {
    extern __shared__ char sm[];
    const int tid = threadIdx.x, lane = tid & 31, wid = tid >> 5;
    const int wm = wid & 3, wn = wid >> 2;
    const int band = blockIdx.z;
    const int m0 = blockIdx.x * 128, n0 = blockIdx.y * 64;

    fill_pad(sm,          g_xnh + ((size_t)band * BTP_ + m0) * C_, C_, 128, tid);
    fill_pad(sm + 34816,  g_xnl + ((size_t)band * BTP_ + m0) * C_, C_, 128, tid);
    fill_pad(sm + 69632,  g_w1h + ((size_t)band * H_ + n0) * C_,   C_, 64,  tid);
    fill_pad(sm + 87040,  g_w1l + ((size_t)band * H_ + n0) * C_,   C_, 64,  tid);
    __syncthreads();

    const uint32_t sb = smem_u32(sm);
    const uint32_t aof = sb + (uint32_t)((wm * 32 + (lane & 15)) * 272 + ((lane >> 4) << 4));
    const uint32_t bof = sb + 69632u +
        (uint32_t)((wn * 32 + (lane & 7) + ((lane >> 4) << 3)) * 272 + (((lane >> 3) & 1) << 4));

    float c[2][4][4] = {};
    #pragma unroll
    for (int sp = 0; sp < 3; ++sp) {
        uint32_t Ab = aof + (sp == 2 ? 34816u : 0u);
        uint32_t Bb = bof + (sp == 1 ? 17408u : 0u);
        #pragma unroll
        for (int k = 0; k < 8; ++k) {
            uint32_t a0[4], a1[4], bA[4], bB[4];
            LDSM4(a0, Ab + k * 32);
            LDSM4(a1, Ab + 16 * 272 + k * 32);
            LDSM4(bA, Bb + k * 32);
            LDSM4(bB, Bb + 16 * 272 + k * 32);
            MMA16816(c[0][0], a0, bA[0], bA[1]);
            MMA16816(c[0][1], a0, bA[2], bA[3]);
            MMA16816(c[0][2], a0, bB[0], bB[1]);
            MMA16816(c[0][3], a0, bB[2], bB[3]);
            MMA16816(c[1][0], a1, bA[0], bA[1]);
            MMA16816(c[1][1], a1, bA[2], bA[3]);
            MMA16816(c[1][2], a1, bB[0], bB[1]);
            MMA16816(c[1][3], a1, bB[2], bB[3]);
        }
    }

    // epilogue: bias + tanh + bf16 hi/lo split store
    const float* b1g = b1 + band * H_;
    __nv_bfloat16* Hh = g_hh + (size_t)band * BTP_ * H_;
    __nv_bfloat16* Hl = g_hl + (size_t)band * BTP_ * H_;
    const int r0 = m0 + wm * 32 + (lane >> 2);
    const int nb0 = n0 + wn * 32 + 2 * (lane & 3);
    #pragma unroll
    for (int ti = 0; ti < 2; ++ti)
        #pragma unroll
        for (int tj = 0; tj < 4; ++tj) {
            int n = nb0 + tj * 8;
            float bx = b1g[n], by = b1g[n + 1];
            #pragma unroll
            for (int h = 0; h < 2; ++h) {
                int m = r0 + ti * 16 + h * 8;
                float v0 = tanh_fast(c[ti][tj][2 * h] + bx);
                float v1 = tanh_fast(c[ti][tj][2 * h + 1] + by);
                store_split(Hh, Hl, (size_t)m * H_ + n, v0, v1);
            }
        }
}

// ============================================================
// fc2: HMMA bf16-split GEMM + GLU + scatter. Templated on band
// width BW (bands grouped contiguously by bw).
// block 128 x NPAD, K=512 in 4 chunks. 8 warps = 4m x 2n; warp
// n-range = HALF cols (warp0 = a-part, warp1 = g-part).
// ============================================================
template<int BW>
__global__ __launch_bounds__(256) void fc2_kernel(const float* __restrict__ b2,
                                                  float* __restrict__ out, int band0) {
    constexpr int NE    = 6 * BW;
    constexpr int HALF  = ((NE + 7) / 8) * 8;
    constexpr int NPAD  = 2 * HALF;
    constexpr int NT    = HALF / 8;
    constexpr int NPAIR = NT / 2;
    constexpr bool ODD  = (NT & 1) != 0;
    constexpr uint32_t WOFF = 69632u;
    constexpr uint32_t WSZ  = (uint32_t)NPAD * 272u;

    extern __shared__ char sm[];
    const int tid = threadIdx.x, lane = tid & 31, wid = tid >> 5;
    const int wm = wid & 3, wn = wid >> 2;
    const int band = band0 + blockIdx.y;
    const int m0 = blockIdx.x * 128;

    const __nv_bfloat16* Ah = g_hh + ((size_t)band * BTP_ + m0) * H_;
    const __nv_bfloat16* Al = g_hl + ((size_t)band * BTP_ + m0) * H_;
    const __nv_bfloat16* Wh = g_w2h + (size_t)band * W2R_ * H_;
    const __nv_bfloat16* Wl = g_w2l + (size_t)band * W2R_ * H_;

    const uint32_t sb = smem_u32(sm);
    const uint32_t aof = sb + (uint32_t)((wm * 32 + (lane & 15)) * 272 + ((lane >> 4) << 4));
    const uint32_t bof = sb + WOFF +
        (uint32_t)((wn * HALF + (lane & 7) + ((lane >> 4) << 3)) * 272 + (((lane >> 3) & 1) << 4));
    const uint32_t bof2 = sb + WOFF +
        (uint32_t)((wn * HALF + (lane & 7)) * 272 + (((lane >> 3) & 1) << 4));

    float c[2][NT][4] = {};
    for (int kc = 0; kc < 4; ++kc) {
        fill_pad(sm,               Ah + kc * 128, H_, 128,  tid);
        fill_pad(sm + 34816,       Al + kc * 128, H_, 128,  tid);
        fill_pad(sm + WOFF,        Wh + kc * 128, H_, NPAD, tid);
        fill_pad(sm + WOFF + WSZ,  Wl + kc * 128, H_, NPAD, tid);
        __syncthreads();
        #pragma unroll
        for (int sp = 0; sp < 3; ++sp) {
            uint32_t Ab = aof + (sp == 2 ? 34816u : 0u);
            uint32_t Bb = (sp == 1 ? WSZ : 0u);
            #pragma unroll
            for (int k = 0; k < 8; ++k) {
                uint32_t a0[4], a1[4];
                LDSM4(a0, Ab + k * 32);
                LDSM4(a1, Ab + 16 * 272 + k * 32);
                #pragma unroll
                for (int tp = 0; tp < NPAIR; ++tp) {
                    uint32_t bb[4];
                    LDSM4(bb, bof + Bb + tp * 16 * 272 + k * 32);
                    MMA16816(c[0][2 * tp],     a0, bb[0], bb[1]);
                    MMA16816(c[0][2 * tp + 1], a0, bb[2], bb[3]);
                    MMA16816(c[1][2 * tp],     a1, bb[0], bb[1]);
                    MMA16816(c[1][2 * tp + 1], a1, bb[2], bb[3]);
                }
                if (ODD) {
                    uint32_t bb[2];
                    LDSM2(bb, bof2 + Bb + (NT - 1) * 8 * 272 + k * 32);
                    MMA16816(c[0][NT - 1], a0, bb[0], bb[1]);
                    MMA16816(c[1][NT - 1], a1, bb[0], bb[1]);
                }
            }
        }
        __syncthreads();
    }

    // stage accum in smem fp32, then GLU + scatter
    float* S = (float*)sm;
    constexpr int SW = NPAD + 4;
    {
        const int r0 = wm * 32 + (lane >> 2);
        const int nb0 = wn * HALF + 2 * (lane & 3);
        #pragma unroll
        for (int ti = 0; ti < 2; ++ti)
            #pragma unroll
            for (int tj = 0; tj < NT; ++tj) {
                int col = nb0 + tj * 8;
                #pragma unroll
                for (int h = 0; h < 2; ++h) {
                    int row = r0 + ti * 16 + h * 8;
                    S[row * SW + col]     = c[ti][tj][2 * h];
                    S[row * SW + col + 1] = c[ti][tj][2 * h + 1];
                }
            }
    }
    __syncthreads();
    const float* b2g = b2 + band * MAXO_;
    const int base = c_base[band];
    for (int idx = tid; idx < 128 * NE; idx += 256) {
        int ml = idx / NE, j = idx - ml * NE;
        int m = m0 + ml;
        if (m < BT_) {
            int bb = m / T_, t = m - bb * T_;
            float a = S[ml * SW + j] + b2g[j];
            float g = S[ml * SW + HALF + j] + b2g[NE + j];
            float r = a * __fdividef(1.f, 1.f + __expf(-g));
            int wv = j / 6, rem = j - wv * 6;
            out[(((size_t)bb * NOUT_ + base + wv) * T_ + t) * 6 + rem] = r;
        }
    }
}

// smem sizes per template: max(tiles, epilogue S)
#define FC2_SMEM_BW(HALFV) ((69632 + 2 * (2 * (HALFV)) * 272) > (128 * (2 * (HALFV) + 4) * 4) ? \
                            (69632 + 2 * (2 * (HALFV)) * 272) : (128 * (2 * (HALFV) + 4) * 4))

// ============================================================
extern "C" void kernel_launch(void* const* d_in, const int* in_sizes, int n_in,
                              void* d_out, int out_size) {
    const float* x  = (const float*)d_in[0];
    const float* nw = (const float*)d_in[1];
    const float* nb = (const float*)d_in[2];
    const float* w1 = (const float*)d_in[3];
    const float* b1 = (const float*)d_in[4];
    const float* w2 = (const float*)d_in[5];
    const float* b2 = (const float*)d_in[6];
    float* out = (float*)d_out;

    const int s2  = FC2_SMEM_BW(16);
    const int s3  = FC2_SMEM_BW(24);
    const int s8  = FC2_SMEM_BW(48);
    const int s16 = FC2_SMEM_BW(96);
    const int s17 = FC2_SMEM_BW(104);

    cudaFuncSetAttribute(fc1_kernel,     cudaFuncAttributeMaxDynamicSharedMemorySize, FC1_SMEM);
    cudaFuncSetAttribute(fc2_kernel<2>,  cudaFuncAttributeMaxDynamicSharedMemorySize, s2);
    cudaFuncSetAttribute(fc2_kernel<3>,  cudaFuncAttributeMaxDynamicSharedMemorySize, s3);
    cudaFuncSetAttribute(fc2_kernel<8>,  cudaFuncAttributeMaxDynamicSharedMemorySize, s8);
    cudaFuncSetAttribute(fc2_kernel<16>, cudaFuncAttributeMaxDynamicSharedMemorySize, s16);
    cudaFuncSetAttribute(fc2_kernel<17>, cudaFuncAttributeMaxDynamicSharedMemorySize, s17);

    zero_stats_kernel<<<1, 128>>>();
    split_w1_kernel<<<512, 256>>>(w1);
    split_w2_kernel<<<512, 256>>>(w2);
    stats_kernel<<<dim3(64, B_), 256>>>(x);
    finalize_stats_kernel<<<1, 128>>>();
    norm_transpose_kernel<<<dim3(T_ / TT, B_), 256>>>(x, nw, nb);
    fc1_kernel<<<dim3(BTP_ / 128, H_ / 64, K_), 256, FC1_SMEM>>>(b1);
    // fc2 per bw-group (bands are contiguous per group)
    fc2_kernel<2> <<<dim3(63, 1),  256, s2 >>>(b2, out, 0);
    fc2_kernel<3> <<<dim3(63, 10), 256, s3 >>>(b2, out, 1);
    fc2_kernel<8> <<<dim3(63, 12), 256, s8 >>>(b2, out, 11);
    fc2_kernel<16><<<dim3(63, 7),  256, s16>>>(b2, out, 23);
    fc2_kernel<17><<<dim3(63, 1),  256, s17>>>(b2, out, 30);
}

// round 16
// speedup vs baseline: 1.9526x; 1.8417x over previous
#include <cuda_runtime.h>
#include <cuda_bf16.h>
#include <math.h>
#include <stdint.h>

#define B_    4
#define C_    128
#define T_    2000
#define K_    31
#define H_    512
#define MAXO_ 204
#define BT_   (B_ * T_)       // 8000
#define BTP_  8064            // padded to 63*128
#define CT_   (C_ * T_)       // 256000
#define NOUT_ 257
#define W2R_  208             // max padded fc2 rows

__constant__ int c_bw[K_]   = {2,3,3,3,3,3,3,3,3,3,3,8,8,8,8,8,8,8,8,8,8,8,8,16,16,16,16,16,16,16,17};
__constant__ int c_base[K_] = {0,2,5,8,11,14,17,20,23,26,29,32,40,48,56,64,72,80,88,96,104,112,120,128,144,160,176,192,208,224,240};

// ---- scratch (device globals) ----
__device__ float g_sum [B_ * K_];
__device__ float g_sq  [B_ * K_];
__device__ float g_mean[B_ * K_];
__device__ float g_istd[B_ * K_];
__device__ __nv_bfloat16 g_xnh[(size_t)K_ * BTP_ * C_];
__device__ __nv_bfloat16 g_xnl[(size_t)K_ * BTP_ * C_];
__device__ __nv_bfloat16 g_hh [(size_t)K_ * BTP_ * H_];
__device__ __nv_bfloat16 g_hl [(size_t)K_ * BTP_ * H_];
__device__ __nv_bfloat16 g_w1h[(size_t)K_ * H_ * C_];
__device__ __nv_bfloat16 g_w1l[(size_t)K_ * H_ * C_];
__device__ __nv_bfloat16 g_w2h[(size_t)K_ * W2R_ * H_];
__device__ __nv_bfloat16 g_w2l[(size_t)K_ * W2R_ * H_];

extern __shared__ char sm[];

// ============================================================
// helpers
// ============================================================
static __device__ __forceinline__ uint32_t smem_u32(const void* p) {
    return (uint32_t)__cvta_generic_to_shared(p);
}

#define LDSM4(r, addr)                                                           \
    asm volatile("ldmatrix.sync.aligned.m8n8.x4.shared.b16 {%0,%1,%2,%3}, [%4];" \
        : "=r"((r)[0]), "=r"((r)[1]), "=r"((r)[2]), "=r"((r)[3]) : "r"(addr))

#define LDSM2(r, addr)                                                           \
    asm volatile("ldmatrix.sync.aligned.m8n8.x2.shared.b16 {%0,%1}, [%2];"       \
        : "=r"((r)[0]), "=r"((r)[1]) : "r"(addr))

#define MMA16816(d, a, b0v, b1v)                                                 \
    asm volatile("mma.sync.aligned.m16n8k16.row.col.f32.bf16.bf16.f32 "          \
        "{%0,%1,%2,%3}, {%4,%5,%6,%7}, {%8,%9}, {%0,%1,%2,%3};"                  \
        : "+f"((d)[0]), "+f"((d)[1]), "+f"((d)[2]), "+f"((d)[3])                 \
        : "r"((a)[0]), "r"((a)[1]), "r"((a)[2]), "r"((a)[3]), "r"(b0v), "r"(b1v))

#define CP16(dst, src)  asm volatile("cp.async.cg.shared.global [%0], [%1], 16;" :: "r"(dst), "l"(src))
#define CP_COMMIT()     asm volatile("cp.async.commit_group;" ::: "memory")
#define CP_WAIT0()      asm volatile("cp.async.wait_group 0;" ::: "memory")
#define CP_WAIT1()      asm volatile("cp.async.wait_group 1;" ::: "memory")

// async fill: rows x (CPR*16 bytes), smem row stride DROW
template<int CPR, int DROW>
static __device__ __forceinline__ void fill_async(uint32_t dst, const __nv_bfloat16* src,
                                                  int gstride, int rows, int tid) {
    const int total = rows * CPR;
    for (int i = tid; i < total; i += 256) {
        int r = i / CPR, cb = i % CPR;
        CP16(dst + r * DROW + cb * 16, src + (size_t)r * gstride + cb * 8);
    }
}

static __device__ __forceinline__ float tanh_fast(float x) {
    float e = __expf(2.0f * x);
    return 1.0f - __fdividef(2.0f, e + 1.0f);
}

static __device__ __forceinline__ void store_split(__nv_bfloat16* Hh, __nv_bfloat16* Hl,
                                                   size_t off, float v0, float v1) {
    __nv_bfloat16 h0 = __float2bfloat16(v0), h1 = __float2bfloat16(v1);
    __nv_bfloat16 l0 = __float2bfloat16(v0 - __bfloat162float(h0));
    __nv_bfloat16 l1 = __float2bfloat16(v1 - __bfloat162float(h1));
    uint32_t hp = (uint32_t)__bfloat16_as_ushort(h0) | ((uint32_t)__bfloat16_as_ushort(h1) << 16);
    uint32_t lp = (uint32_t)__bfloat16_as_ushort(l0) | ((uint32_t)__bfloat16_as_ushort(l1) << 16);
    *(uint32_t*)(Hh + off) = hp;
    *(uint32_t*)(Hl + off) = lp;
}

// ============================================================
// stats
// ============================================================
__global__ void zero_stats_kernel() {
    int i = threadIdx.x;
    if (i < B_ * K_) { g_sum[i] = 0.f; g_sq[i] = 0.f; }
}

__global__ __launch_bounds__(256) void stats_kernel(const float* __restrict__ x) {
    const int b    = blockIdx.y;
    const int lane = threadIdx.x & 31;
    const int warp = threadIdx.x >> 5;
    const int ROWS_PER_BLOCK = CT_ / 64;
    const int ROWS_PER_WARP  = ROWS_PER_BLOCK / 8;
    const int r0 = blockIdx.x * ROWS_PER_BLOCK + warp * ROWS_PER_WARP;

    float s = 0.f, q = 0.f;
    if (lane < K_) {
        const float* p = x + (size_t)b * CT_ * K_ + (size_t)r0 * K_ + lane;
        #pragma unroll 8
        for (int r = 0; r < ROWS_PER_WARP; ++r) {
            float v = p[(size_t)r * K_];
            s += v; q += v * v;
        }
    }
    __shared__ float ss[8][32], sq[8][32];
    ss[warp][lane] = s; sq[warp][lane] = q;
    __syncthreads();
    if (warp == 0 && lane < K_) {
        float S = 0.f, Q = 0.f;
        #pragma unroll
        for (int w = 0; w < 8; ++w) { S += ss[w][lane]; Q += sq[w][lane]; }
        atomicAdd(&g_sum[b * K_ + lane], S);
        atomicAdd(&g_sq [b * K_ + lane], Q);
    }
}

__global__ void finalize_stats_kernel() {
    int i = threadIdx.x;
    if (i < B_ * K_) {
        const float n = (float)CT_;
        float m = g_sum[i] / n;
        float v = g_sq[i] / n - m * m;
        g_mean[i] = m;
        g_istd[i] = rsqrtf(v + 1e-5f);
    }
}

// ============================================================
// normalize + transpose + bf16 hi/lo split  (TT=4, dyn smem)
// ============================================================
#define TT 4
#define NORM_SMEM (TT * K_ * (C_ + 1) * 4)   // 63984

__global__ __launch_bounds__(256) void norm_transpose_kernel(
        const float* __restrict__ x,
        const float* __restrict__ nw,
        const float* __restrict__ nb) {
    float* tile = (float*)sm;                 // [TT][K_][C_+1]
    const int b  = blockIdx.y;
    const int t0 = blockIdx.x * TT;
    const int NEL = C_ * TT * K_;

    for (int idx = threadIdx.x; idx < NEL; idx += blockDim.x) {
        int c = idx / (TT * K_);
        int r = idx % (TT * K_);
        int t = r / K_;
        int k = r % K_;
        float v = x[(((size_t)b * C_ + c) * T_ + (t0 + t)) * K_ + k];
        int bk = b * K_ + k;
        v = (v - g_mean[bk]) * g_istd[bk] * nw[k * C_ + c] + nb[k * C_ + c];
        tile[(t * K_ + k) * (C_ + 1) + c] = v;
    }
    __syncthreads();
    for (int idx = threadIdx.x; idx < NEL; idx += blockDim.x) {
        int row = idx / C_;        // 0..TT*K_-1
        int c   = idx % C_;
        int k   = row >> 2;
        int t   = row & 3;
        float v = tile[(t * K_ + k) * (C_ + 1) + c];
        __nv_bfloat16 hi = __float2bfloat16(v);
        __nv_bfloat16 lo = __float2bfloat16(v - __bfloat162float(hi));
        size_t o = ((size_t)k * BTP_ + (size_t)b * T_ + t0 + t) * C_ + c;
        g_xnh[o] = hi;
        g_xnl[o] = lo;
    }
}

// ============================================================
// weight splits
// ============================================================
__global__ void split_w1_kernel(const float* __restrict__ w1) {
    size_t n = (size_t)K_ * H_ * C_;
    for (size_t i = blockIdx.x * blockDim.x + threadIdx.x; i < n;
         i += (size_t)gridDim.x * blockDim.x) {
        float v = w1[i];
        __nv_bfloat16 hi = __float2bfloat16(v);
        g_w1h[i] = hi;
        g_w1l[i] = __float2bfloat16(v - __bfloat162float(hi));
    }
}

__global__ void split_w2_kernel(const float* __restrict__ w2) {
    size_t n = (size_t)K_ * W2R_ * H_;
    for (size_t i = blockIdx.x * blockDim.x + threadIdx.x; i < n;
         i += (size_t)gridDim.x * blockDim.x) {
        int c = (int)(i % H_);
        int r = (int)((i / H_) % W2R_);
        int k = (int)(i / ((size_t)W2R_ * H_));
        int neff6 = 6 * c_bw[k];
        int half  = ((neff6 + 7) >> 3) << 3;
        float v = 0.f;
        if (r < half) {
            if (r < neff6) v = w2[((size_t)k * MAXO_ + r) * H_ + c];
        } else {
            int gidx = r - half;
            if (gidx < neff6) v = w2[((size_t)k * MAXO_ + neff6 + gidx) * H_ + c];
        }
        __nv_bfloat16 hi = __float2bfloat16(v);
        g_w2h[i] = hi;
        g_w2l[i] = __float2bfloat16(v - __bfloat162float(hi));
    }
}

// ============================================================
// fc1: A-resident, n-chunk loop, cp.async double-buffered W.
// grid (63, 31). A hi/lo 128x128 (272B rows); W chunks 64x128.
// 8 warps = 4m x 2n over 128x64 chunk.
// smem: A_hi 0, A_lo 34816, Wbuf0 69632 (hi+lo 34816), Wbuf1 104448
// ============================================================
#define FC1_SMEM 139264

__global__ __launch_bounds__(256) void fc1_kernel(const float* __restrict__ b1) {
    const int tid = threadIdx.x, lane = tid & 31, wid = tid >> 5;
    const int wm = wid & 3, wn = wid >> 2;
    const int band = blockIdx.y;
    const int m0 = blockIdx.x * 128;
    const uint32_t sb = smem_u32(sm);

    const __nv_bfloat16* W1h = g_w1h + (size_t)band * H_ * C_;
    const __nv_bfloat16* W1l = g_w1l + (size_t)band * H_ * C_;

    // A (once) + W chunk 0 — one cp.async group
    fill_async<16, 272>(sb,          g_xnh + ((size_t)band * BTP_ + m0) * C_, C_, 128, tid);
    fill_async<16, 272>(sb + 34816,  g_xnl + ((size_t)band * BTP_ + m0) * C_, C_, 128, tid);
    fill_async<16, 272>(sb + 69632,  W1h, C_, 64, tid);
    fill_async<16, 272>(sb + 87040,  W1l, C_, 64, tid);
    CP_COMMIT();

    const uint32_t aof = sb + (uint32_t)((wm * 32 + (lane & 15)) * 272 + ((lane >> 4) << 4));
    const uint32_t bofl = (uint32_t)((wn * 32 + (lane & 7) + ((lane >> 4) << 3)) * 272
                                     + (((lane >> 3) & 1) << 4));

    const float* b1g = b1 + band * H_;
    __nv_bfloat16* Hh = g_hh + (size_t)band * BTP_ * H_;
    __nv_bfloat16* Hl = g_hl + (size_t)band * BTP_ * H_;

    for (int nc = 0; nc < 8; ++nc) {
        if (nc < 7) {   // prefetch next W chunk into other buffer
            uint32_t wb = sb + 69632u + (uint32_t)(((nc + 1) & 1) * 34816);
            fill_async<16, 272>(wb,          W1h + (size_t)(nc + 1) * 64 * C_, C_, 64, tid);
            fill_async<16, 272>(wb + 17408,  W1l + (size_t)(nc + 1) * 64 * C_, C_, 64, tid);
            CP_COMMIT();
            CP_WAIT1();
        } else {
            CP_WAIT0();
        }
        __syncthreads();

        const uint32_t wbase = sb + 69632u + (uint32_t)((nc & 1) * 34816);
        float c[2][4][4] = {};
        #pragma unroll
        for (int sp = 0; sp < 3; ++sp) {
            uint32_t Ab = aof + (sp == 2 ? 34816u : 0u);
            uint32_t Bb = wbase + bofl + (sp == 1 ? 17408u : 0u);
            #pragma unroll
            for (int k = 0; k < 8; ++k) {
                uint32_t a0[4], a1[4], bA[4];
                LDSM4(a0, Ab + k * 32);
                LDSM4(a1, Ab + 16 * 272 + k * 32);
                LDSM4(bA, Bb + k * 32);
                MMA16816(c[0][0], a0, bA[0], bA[1]);
                MMA16816(c[0][1], a0, bA[2], bA[3]);
                MMA16816(c[1][0], a1, bA[0], bA[1]);
                MMA16816(c[1][1], a1, bA[2], bA[3]);
                uint32_t bB[4];
                LDSM4(bB, Bb + 16 * 272 + k * 32);
                MMA16816(c[0][2], a0, bB[0], bB[1]);
                MMA16816(c[0][3], a0, bB[2], bB[3]);
                MMA16816(c[1][2], a1, bB[0], bB[1]);
                MMA16816(c[1][3], a1, bB[2], bB[3]);
            }
        }

        // epilogue for this 64-col chunk (overlaps next W prefetch)
        const int r0 = m0 + wm * 32 + (lane >> 2);
        const int nb0 = nc * 64 + wn * 32 + 2 * (lane & 3);
        #pragma unroll
        for (int ti = 0; ti < 2; ++ti)
            #pragma unroll
            for (int tj = 0; tj < 4; ++tj) {
                int n = nb0 + tj * 8;
                float bx = b1g[n], by = b1g[n + 1];
                #pragma unroll
                for (int h = 0; h < 2; ++h) {
                    int m = r0 + ti * 16 + h * 8;
                    float v0 = tanh_fast(c[ti][tj][2 * h] + bx);
                    float v1 = tanh_fast(c[ti][tj][2 * h + 1] + by);
                    store_split(Hh, Hl, (size_t)m * H_ + n, v0, v1);
                }
            }
        __syncthreads();
    }
}

// ============================================================
// fc2: K chunks of 64, cp.async double-buffered A+W (144B rows).
// Templated on band width BW. 8 warps = 4m x 2n(HALF).
// buf layout: A_hi(18432) A_lo(18432) W_hi(NPAD*144) W_lo(NPAD*144)
// ============================================================
template<int BW>
__global__ __launch_bounds__(256) void fc2_kernel(const float* __restrict__ b2,
                                                  float* __restrict__ out, int band0) {
    constexpr int NE    = 6 * BW;
    constexpr int HALF  = ((NE + 7) / 8) * 8;
    constexpr int NPAD  = 2 * HALF;
    constexpr int NT    = HALF / 8;
    constexpr int NPAIR = NT / 2;
    constexpr bool ODD  = (NT & 1) != 0;
    constexpr uint32_t WSZ   = (uint32_t)NPAD * 144u;      // one W matrix
    constexpr uint32_t BUFSZ = 36864u + 2u * WSZ;          // A hi+lo + W hi+lo

    const int tid = threadIdx.x, lane = tid & 31, wid = tid >> 5;
    const int wm = wid & 3, wn = wid >> 2;
    const int band = band0 + blockIdx.y;
    const int m0 = blockIdx.x * 128;
    const uint32_t sb = smem_u32(sm);

    const __nv_bfloat16* Ah = g_hh + ((size_t)band * BTP_ + m0) * H_;
    const __nv_bfloat16* Al = g_hl + ((size_t)band * BTP_ + m0) * H_;
    const __nv_bfloat16* Wh = g_w2h + (size_t)band * W2R_ * H_;
    const __nv_bfloat16* Wl = g_w2l + (size_t)band * W2R_ * H_;

    // prefetch chunk 0
    fill_async<8, 144>(sb,                 Ah, H_, 128,  tid);
    fill_async<8, 144>(sb + 18432,         Al, H_, 128,  tid);
    fill_async<8, 144>(sb + 36864,         Wh, H_, NPAD, tid);
    fill_async<8, 144>(sb + 36864 + WSZ,   Wl, H_, NPAD, tid);
    CP_COMMIT();

    const uint32_t aofl = (uint32_t)((wm * 32 + (lane & 15)) * 144 + ((lane >> 4) << 4));
    const uint32_t bofl = (uint32_t)((wn * HALF + (lane & 7) + ((lane >> 4) << 3)) * 144
                                     + (((lane >> 3) & 1) << 4));
    const uint32_t bofl2 = (uint32_t)((wn * HALF + (lane & 7)) * 144 + (((lane >> 3) & 1) << 4));

    float c[2][NT][4] = {};
    for (int kc = 0; kc < 8; ++kc) {
        if (kc < 7) {
            uint32_t nb = sb + (uint32_t)(((kc + 1) & 1)) * BUFSZ;
            const int ko = (kc + 1) * 64;
            fill_async<8, 144>(nb,               Ah + ko, H_, 128,  tid);
            fill_async<8, 144>(nb + 18432,       Al + ko, H_, 128,  tid);
            fill_async<8, 144>(nb + 36864,       Wh + ko, H_, NPAD, tid);
            fill_async<8, 144>(nb + 36864 + WSZ, Wl + ko, H_, NPAD, tid);
            CP_COMMIT();
            CP_WAIT1();
        } else {
            CP_WAIT0();
        }
        __syncthreads();

        const uint32_t bb0 = sb + (uint32_t)((kc & 1)) * BUFSZ;
        #pragma unroll
        for (int sp = 0; sp < 3; ++sp) {
            uint32_t Ab = bb0 + aofl + (sp == 2 ? 18432u : 0u);
            uint32_t Bb = bb0 + 36864u + (sp == 1 ? WSZ : 0u);
            #pragma unroll
            for (int k = 0; k < 4; ++k) {
                uint32_t a0[4], a1[4];
                LDSM4(a0, Ab + k * 32);
                LDSM4(a1, Ab + 16 * 144 + k * 32);
                #pragma unroll
                for (int tp = 0; tp < NPAIR; ++tp) {
                    uint32_t bb[4];
                    LDSM4(bb, Bb + bofl + tp * 16 * 144 + k * 32);
                    MMA16816(c[0][2 * tp],     a0, bb[0], bb[1]);
                    MMA16816(c[0][2 * tp + 1], a0, bb[2], bb[3]);
                    MMA16816(c[1][2 * tp],     a1, bb[0], bb[1]);
                    MMA16816(c[1][2 * tp + 1], a1, bb[2], bb[3]);
                }
                if (ODD) {
                    uint32_t bb[2];
                    LDSM2(bb, Bb + bofl2 + (NT - 1) * 8 * 144 + k * 32);
                    MMA16816(c[0][NT - 1], a0, bb[0], bb[1]);
                    MMA16816(c[1][NT - 1], a1, bb[0], bb[1]);
                }
            }
        }
        __syncthreads();
    }

    // stage accum in smem fp32, then GLU + scatter
    float* S = (float*)sm;
    constexpr int SW = NPAD + 4;
    {
        const int r0 = wm * 32 + (lane >> 2);
        const int nb0 = wn * HALF + 2 * (lane & 3);
        #pragma unroll
        for (int ti = 0; ti < 2; ++ti)
            #pragma unroll
            for (int tj = 0; tj < NT; ++tj) {
                int col = nb0 + tj * 8;
                #pragma unroll
                for (int h = 0; h < 2; ++h) {
                    int row = r0 + ti * 16 + h * 8;
                    S[row * SW + col]     = c[ti][tj][2 * h];
                    S[row * SW + col + 1] = c[ti][tj][2 * h + 1];
                }
            }
    }
    __syncthreads();
    const float* b2g = b2 + band * MAXO_;
    const int base = c_base[band];
    for (int idx = tid; idx < 128 * NE; idx += 256) {
        int ml = idx / NE, j = idx - ml * NE;
        int m = m0 + ml;
        if (m < BT_) {
            int bb = m / T_, t = m - bb * T_;
            float a = S[ml * SW + j] + b2g[j];
            float g = S[ml * SW + HALF + j] + b2g[NE + j];
            float r = a * __fdividef(1.f, 1.f + __expf(-g));
            int wv = j / 6, rem = j - wv * 6;
            out[(((size_t)bb * NOUT_ + base + wv) * T_ + t) * 6 + rem] = r;
        }
    }
}

#define FC2_SMEM_BW(HALFV) (2 * (36864 + 2 * (2 * (HALFV)) * 144))

// ============================================================
extern "C" void kernel_launch(void* const* d_in, const int* in_sizes, int n_in,
                              void* d_out, int out_size) {
    const float* x  = (const float*)d_in[0];
    const float* nw = (const float*)d_in[1];
    const float* nb = (const float*)d_in[2];
    const float* w1 = (const float*)d_in[3];
    const float* b1 = (const float*)d_in[4];
    const float* w2 = (const float*)d_in[5];
    const float* b2 = (const float*)d_in[6];
    float* out = (float*)d_out;

    const int s2  = FC2_SMEM_BW(16);    //  92160
    const int s3  = FC2_SMEM_BW(24);    // 101376
    const int s8  = FC2_SMEM_BW(48);    // 129024
    const int s16 = FC2_SMEM_BW(96);    // 184320
    const int s17 = FC2_SMEM_BW(104);   // 193536

    cudaFuncSetAttribute(norm_transpose_kernel, cudaFuncAttributeMaxDynamicSharedMemorySize, NORM_SMEM);
    cudaFuncSetAttribute(fc1_kernel,     cudaFuncAttributeMaxDynamicSharedMemorySize, FC1_SMEM);
    cudaFuncSetAttribute(fc2_kernel<2>,  cudaFuncAttributeMaxDynamicSharedMemorySize, s2);
    cudaFuncSetAttribute(fc2_kernel<3>,  cudaFuncAttributeMaxDynamicSharedMemorySize, s3);
    cudaFuncSetAttribute(fc2_kernel<8>,  cudaFuncAttributeMaxDynamicSharedMemorySize, s8);
    cudaFuncSetAttribute(fc2_kernel<16>, cudaFuncAttributeMaxDynamicSharedMemorySize, s16);
    cudaFuncSetAttribute(fc2_kernel<17>, cudaFuncAttributeMaxDynamicSharedMemorySize, s17);

    zero_stats_kernel<<<1, 128>>>();
    split_w1_kernel<<<512, 256>>>(w1);
    split_w2_kernel<<<512, 256>>>(w2);
    stats_kernel<<<dim3(64, B_), 256>>>(x);
    finalize_stats_kernel<<<1, 128>>>();
    norm_transpose_kernel<<<dim3(T_ / TT, B_), 256, NORM_SMEM>>>(x, nw, nb);
    fc1_kernel<<<dim3(BTP_ / 128, K_), 256, FC1_SMEM>>>(b1);
    fc2_kernel<2> <<<dim3(63, 1),  256, s2 >>>(b2, out, 0);
    fc2_kernel<3> <<<dim3(63, 10), 256, s3 >>>(b2, out, 1);
    fc2_kernel<8> <<<dim3(63, 12), 256, s8 >>>(b2, out, 11);
    fc2_kernel<16><<<dim3(63, 7),  256, s16>>>(b2, out, 23);
    fc2_kernel<17><<<dim3(63, 1),  256, s17>>>(b2, out, 30);
}